// round 1
// baseline (speedup 1.0000x reference)
#include <cuda_runtime.h>
#include <cstdint>

#define DIN  256
#define DOUT 64
#define NMAX 200000

// Scratch (no allocations allowed): projected embeddings + per-node src score
__device__ float g_eprime[(size_t)NMAX * DOUT];
__device__ float g_ssrc[NMAX];
__device__ int   g_mask_is_byte;

// ---------------- packed f32x2 helpers (SASS FFMA2: 2x fp32 FMA per instr) ---
__device__ __forceinline__ unsigned long long fma2(unsigned long long a,
                                                   unsigned long long b,
                                                   unsigned long long c) {
    asm("fma.rn.f32x2 %0, %1, %2, %3;" : "=l"(c) : "l"(a), "l"(b), "l"(c));
    return c;
}
__device__ __forceinline__ unsigned long long dup2(float x) {
    unsigned long long r;
    asm("mov.b64 %0, {%1, %1};" : "=l"(r) : "f"(x));
    return r;
}
__device__ __forceinline__ float2 unpack2(unsigned long long v) {
    float2 f;
    asm("mov.b64 {%0, %1}, %2;" : "=f"(f.x), "=f"(f.y) : "l"(v));
    return f;
}

// ---------------- Phase 1: Y[N,64] = X[N,256] @ W[64,256]^T --------------------
// BM=128 rows, BN=64 (all cols), BK=64. 256 threads, 8x4 outputs/thread via f32x2.
__global__ __launch_bounds__(256) void gemm_kernel(const float* __restrict__ X,
                                                   const float* __restrict__ W,
                                                   int N) {
    __shared__ float As[64][128];  // [k][m]  (transposed store, conflict-free)
    __shared__ float Ws[64][64];   // [k][n]

    const int t    = threadIdx.x;
    const int row0 = blockIdx.x * 128;

    // X-tile load mapping: lane-consecutive rows -> conflict-free STS
    const int mL    = t & 127;
    const int kHalf = (t >> 7) * 8;       // 0 or 8
    // W-tile load mapping
    const int nW  = t & 63;
    const int kqW = (t >> 6) * 16;        // 0,16,32,48
    // compute mapping
    const int tx = t & 15, ty = t >> 4;
    const int m0 = ty * 8, n0 = tx * 4;

    unsigned long long acc[4][4];
#pragma unroll
    for (int i = 0; i < 4; i++)
#pragma unroll
        for (int j = 0; j < 4; j++) acc[i][j] = 0ull;

    const bool rowValid = (row0 + mL) < N;
    const float* xrow = X + (size_t)(row0 + mL) * DIN;
    const float* wrow = W + (size_t)nW * DIN;

    for (int kc = 0; kc < DIN; kc += 64) {
        // ---- load X tile (each thread: 4 passes x 32B) ----
#pragma unroll
        for (int p = 0; p < 4; p++) {
            int kl = p * 16 + kHalf;
            float4 v0, v1;
            if (rowValid) {
                const float* src = xrow + kc + kl;
                v0 = *(const float4*)(src);
                v1 = *(const float4*)(src + 4);
            } else {
                v0 = make_float4(0.f, 0.f, 0.f, 0.f);
                v1 = v0;
            }
            As[kl + 0][mL] = v0.x; As[kl + 1][mL] = v0.y;
            As[kl + 2][mL] = v0.z; As[kl + 3][mL] = v0.w;
            As[kl + 4][mL] = v1.x; As[kl + 5][mL] = v1.y;
            As[kl + 6][mL] = v1.z; As[kl + 7][mL] = v1.w;
        }
        // ---- load W tile (64B/thread) ----
        {
            const float* srcw = wrow + kc + kqW;
#pragma unroll
            for (int u = 0; u < 4; u++) {
                float4 w4 = *(const float4*)(srcw + u * 4);
                Ws[kqW + u * 4 + 0][nW] = w4.x;
                Ws[kqW + u * 4 + 1][nW] = w4.y;
                Ws[kqW + u * 4 + 2][nW] = w4.z;
                Ws[kqW + u * 4 + 3][nW] = w4.w;
            }
        }
        __syncthreads();

#pragma unroll 16
        for (int k = 0; k < 64; k++) {
            ulonglong2 A0 = *(const ulonglong2*)(&As[k][m0]);
            ulonglong2 A1 = *(const ulonglong2*)(&As[k][m0 + 4]);
            float4 bv = *(const float4*)(&Ws[k][n0]);
            unsigned long long a2[4] = {A0.x, A0.y, A1.x, A1.y};
            unsigned long long bd[4] = {dup2(bv.x), dup2(bv.y), dup2(bv.z), dup2(bv.w)};
#pragma unroll
            for (int i = 0; i < 4; i++)
#pragma unroll
                for (int j = 0; j < 4; j++)
                    acc[i][j] = fma2(a2[i], bd[j], acc[i][j]);
        }
        __syncthreads();
    }

    // ---- epilogue: unpack + coalesced float4 stores ----
#pragma unroll
    for (int i = 0; i < 4; i++) {
        float2 u0 = unpack2(acc[i][0]);
        float2 u1 = unpack2(acc[i][1]);
        float2 u2 = unpack2(acc[i][2]);
        float2 u3 = unpack2(acc[i][3]);
        int r0 = row0 + m0 + 2 * i;
        if (r0 < N)
            *(float4*)(&g_eprime[(size_t)r0 * DOUT + n0]) =
                make_float4(u0.x, u1.x, u2.x, u3.x);
        if (r0 + 1 < N)
            *(float4*)(&g_eprime[(size_t)(r0 + 1) * DOUT + n0]) =
                make_float4(u0.y, u1.y, u2.y, u3.y);
    }
}

// ---------------- Phase 1b: s_src[n] = leaky_relu(e'[n] . a_src) ---------------
__global__ __launch_bounds__(256) void ssrc_kernel(const float* __restrict__ a_src,
                                                   int N) {
    int row  = blockIdx.x * 8 + (threadIdx.x >> 5);
    int lane = threadIdx.x & 31;
    if (row >= N) return;
    const float2* yr = (const float2*)(g_eprime + (size_t)row * DOUT);
    float2 v = yr[lane];
    float a0 = __ldg(&a_src[2 * lane]);
    float a1 = __ldg(&a_src[2 * lane + 1]);
    float p = v.x * a0 + v.y * a1;
#pragma unroll
    for (int o = 16; o; o >>= 1) p += __shfl_xor_sync(0xffffffffu, p, o);
    if (lane == 0) g_ssrc[row] = (p >= 0.f) ? p : 0.2f * p;
}

// ---------------- mask dtype probe: bool(1B) vs int32 --------------------------
__global__ void detect_kernel(const unsigned char* __restrict__ m) {
    if (threadIdx.x == 0 && blockIdx.x == 0) {
        int f = 0;
        for (int i = 0; i < 256; i++)
            if ((i & 3) && m[i]) f = 1;   // int32 {0,1} has bytes 1..3 == 0
        g_mask_is_byte = f;
    }
}

// ---------------- Phase 2: masked softmax + weighted gather-sum ----------------
// One warp per output row. L <= 64.
__global__ __launch_bounds__(256) void agg_kernel(const int* __restrict__ neighs,
                                                  const void* __restrict__ mask_raw,
                                                  float* __restrict__ out,
                                                  int B, int L) {
    __shared__ float sw[8][64];
    __shared__ int   sidx[8][64];

    const int w    = threadIdx.x >> 5;
    const int lane = threadIdx.x & 31;
    const int row  = blockIdx.x * 8 + w;
    if (row >= B) return;

    const bool maskb = (g_mask_is_byte != 0);
    const unsigned char* mk8  = (const unsigned char*)mask_raw + (size_t)row * L;
    const int*           mk32 = (const int*)mask_raw + (size_t)row * L;
    const int* nb = neighs + (size_t)row * L;

    // gather up to 2 neighbor slots per lane
    int   i0 = 0, i1 = 0;
    float s0 = -3e38f, s1 = -3e38f;
    bool  v0 = false, v1 = false;
    if (lane < L) {
        v0 = maskb ? (mk8[lane] != 0) : (mk32[lane] != 0);
        if (v0) { i0 = nb[lane]; s0 = g_ssrc[i0]; }
    }
    int l1 = lane + 32;
    if (l1 < L) {
        v1 = maskb ? (mk8[l1] != 0) : (mk32[l1] != 0);
        if (v1) { i1 = nb[l1]; s1 = g_ssrc[i1]; }
    }

    // softmax over valid slots (dst term cancels; masked -> exact 0 weight)
    float m = fmaxf(s0, s1);
#pragma unroll
    for (int o = 16; o; o >>= 1) m = fmaxf(m, __shfl_xor_sync(0xffffffffu, m, o));
    float e0 = v0 ? __expf(s0 - m) : 0.f;
    float e1 = v1 ? __expf(s1 - m) : 0.f;
    float ssum = e0 + e1;
#pragma unroll
    for (int o = 16; o; o >>= 1) ssum += __shfl_xor_sync(0xffffffffu, ssum, o);
    float inv = 1.0f / ssum;

    // ballot-compaction of valid (weight, index) pairs into shared
    unsigned bal0 = __ballot_sync(0xffffffffu, v0);
    unsigned bal1 = __ballot_sync(0xffffffffu, v1);
    int c0  = __popc(bal0);
    int cnt = c0 + __popc(bal1);
    unsigned lt = (1u << lane) - 1u;
    if (v0) { int p = __popc(bal0 & lt);       sw[w][p] = e0 * inv; sidx[w][p] = i0; }
    if (v1) { int p = c0 + __popc(bal1 & lt);  sw[w][p] = e1 * inv; sidx[w][p] = i1; }
    __syncwarp();

    // weighted sum: lane owns dims 2*lane, 2*lane+1 -> coalesced 256B row reads
    float acc0 = 0.f, acc1 = 0.f;
    for (int l = 0; l < cnt; l++) {
        float wgt = sw[w][l];
        const float2 v = *(const float2*)(g_eprime + (size_t)sidx[w][l] * DOUT + 2 * lane);
        acc0 = fmaf(wgt, v.x, acc0);
        acc1 = fmaf(wgt, v.y, acc1);
    }
    *(float2*)(&out[(size_t)row * DOUT + 2 * lane]) = make_float2(acc0, acc1);
}

// -------------------------------------------------------------------------------
extern "C" void kernel_launch(void* const* d_in, const int* in_sizes, int n_in,
                              void* d_out, int out_size) {
    const int*   neighs = (const int*)d_in[0];
    const void*  mask   = d_in[1];
    const float* embed  = (const float*)d_in[3];
    const float* W      = (const float*)d_in[4];
    const float* a_src  = (const float*)d_in[5];

    const int B = in_sizes[2];
    const int L = in_sizes[0] / B;
    const int N = in_sizes[3] / DIN;

    gemm_kernel<<<(N + 127) / 128, 256>>>(embed, W, N);
    ssrc_kernel<<<(N + 7) / 8, 256>>>(a_src, N);
    detect_kernel<<<1, 32>>>((const unsigned char*)mask);
    agg_kernel<<<(B + 7) / 8, 256>>>(neighs, mask, (float*)d_out, B, L);
}

// round 3
// speedup vs baseline: 1.2116x; 1.2116x over previous
#include <cuda_runtime.h>
#include <cuda_bf16.h>
#include <cstdint>

#define DIN  256
#define DOUT 64
#define NMAX 200000

// ---------------- device scratch (no allocations allowed) ----------------------
__device__ float g_eprime[(size_t)NMAX * DOUT];
__device__ float g_ssrc[NMAX];
__device__ __nv_bfloat16 g_Whi[DOUT * DIN];
__device__ __nv_bfloat16 g_Wlo[DOUT * DIN];
__device__ int g_mask_is_byte;

// ---------------- helpers -------------------------------------------------------
__device__ __forceinline__ uint32_t smem_u32(const void* p) {
    uint32_t a;
    asm("{ .reg .u64 t; cvta.to.shared.u64 t, %1; cvt.u32.u64 %0, t; }" : "=r"(a) : "l"(p));
    return a;
}
#define SWZ128(bo) ((bo) ^ (((bo) >> 3) & 0x70))

__device__ __forceinline__ void ldsm_x4(uint32_t* r, uint32_t addr) {
    asm volatile("ldmatrix.sync.aligned.m8n8.x4.shared.b16 {%0,%1,%2,%3}, [%4];"
                 : "=r"(r[0]), "=r"(r[1]), "=r"(r[2]), "=r"(r[3]) : "r"(addr));
}
__device__ __forceinline__ void mma_bf16(float* c, const uint32_t* a,
                                         uint32_t b0, uint32_t b1) {
    asm volatile("mma.sync.aligned.m16n8k16.row.col.f32.bf16.bf16.f32 "
                 "{%0,%1,%2,%3}, {%4,%5,%6,%7}, {%8,%9}, {%0,%1,%2,%3};"
                 : "+f"(c[0]), "+f"(c[1]), "+f"(c[2]), "+f"(c[3])
                 : "r"(a[0]), "r"(a[1]), "r"(a[2]), "r"(a[3]), "r"(b0), "r"(b1));
}

// split a float into bf16 hi (round-half-up, 2 int ops) + fp32 residual
__device__ __forceinline__ uint32_t hi_bits(float x) {
    return (__float_as_uint(x) + 0x8000u) & 0xFFFF0000u;
}

// ---------------- smem layout ----------------------------------------------------
#define STAGE_BYTES 32768     // AHI 16KB + ALO 16KB
#define OFF_ALO     16384
#define SMEM_TOTAL  (2 * STAGE_BYTES)

// ---------------- W split (once per launch) --------------------------------------
__global__ void wsplit_kernel(const float* __restrict__ W) {
    int i = blockIdx.x * 256 + threadIdx.x;
    if (i < DOUT * DIN) {
        float x  = W[i];
        float hf = __uint_as_float(hi_bits(x));
        g_Whi[i] = __float2bfloat16_rn(hf);      // exact (already bf16 value)
        g_Wlo[i] = __float2bfloat16_rn(x - hf);
    }
}

// ---------------- Phase 1: mma.sync bf16 3-pass GEMM -----------------------------
// Y[N,64] = X[N,256] @ W[64,256]^T, fp32-accurate via (Ahi+Alo)(Whi+Wlo) - Alo*Wlo
__global__ __launch_bounds__(256, 2) void gemm_mma_kernel(const float* __restrict__ X,
                                                          int Ntot) {
    extern __shared__ char smem[];
    const uint32_t sb = smem_u32(smem);

    const int t    = threadIdx.x;
    const int lane = t & 31;
    const int wid  = t >> 5;
    const int row0 = blockIdx.x * 128;

    const int m0 = (wid & 3) * 32;   // warp m-offset within tile
    const int n0 = (wid >> 2) * 32;  // warp n-offset

    // staging mapping: thread handles rows (t>>3)+32p, 8-float group g=t&7
    const int srow = t >> 3, g = t & 7;

    // ldmatrix lane geometry
    const int r_lm   = (lane & 7) | (((lane >> 3) & 1) << 3);  // row 0-15 in tile
    const int klane  = ((lane >> 4) & 1) * 16;                 // 16B half select

    // B-frag lane geometry: n = +lane/4, k pair = (lane&3)*2
    const int bn = lane >> 2, bk = (lane & 3) * 2;

    float acc[2][4][4];
#pragma unroll
    for (int i = 0; i < 2; i++)
#pragma unroll
        for (int j = 0; j < 4; j++)
#pragma unroll
            for (int q = 0; q < 4; q++) acc[i][j][q] = 0.f;

    // clamped global rows for loads (guarded stores later)
    size_t grow[4];
#pragma unroll
    for (int p = 0; p < 4; p++) {
        int r = row0 + srow + 32 * p;
        grow[p] = (size_t)((r < Ntot) ? r : (Ntot - 1));
    }

    float4 va[4][2];
    // ---- prologue: load + stage chunk 0 ----
#pragma unroll
    for (int p = 0; p < 4; p++) {
        const float* src = X + grow[p] * DIN + g * 8;
        va[p][0] = *(const float4*)(src);
        va[p][1] = *(const float4*)(src + 4);
    }
    {
        char* st = smem;  // stage 0
#pragma unroll
        for (int p = 0; p < 4; p++) {
            uint32_t rh[4], rl[4];
            float f[8] = {va[p][0].x, va[p][0].y, va[p][0].z, va[p][0].w,
                          va[p][1].x, va[p][1].y, va[p][1].z, va[p][1].w};
#pragma unroll
            for (int q = 0; q < 4; q++) {
                uint32_t ha = hi_bits(f[2 * q]), hb = hi_bits(f[2 * q + 1]);
                rh[q] = __byte_perm(ha, hb, 0x7632);
                __nv_bfloat162 lo2 = __floats2bfloat162_rn(
                    f[2 * q] - __uint_as_float(ha), f[2 * q + 1] - __uint_as_float(hb));
                rl[q] = *(uint32_t*)&lo2;
            }
            uint32_t bo = SWZ128((uint32_t)(srow + 32 * p) * 128 + g * 16);
            *(uint4*)(st + bo)           = make_uint4(rh[0], rh[1], rh[2], rh[3]);
            *(uint4*)(st + OFF_ALO + bo) = make_uint4(rl[0], rl[1], rl[2], rl[3]);
        }
    }
    __syncthreads();

    for (int c = 0; c < 4; c++) {
        // ---- prefetch next chunk's gmem while computing this one ----
        if (c < 3) {
            const int kc = (c + 1) * 64;
#pragma unroll
            for (int p = 0; p < 4; p++) {
                const float* src = X + grow[p] * DIN + kc + g * 8;
                va[p][0] = *(const float4*)(src);
                va[p][1] = *(const float4*)(src + 4);
            }
        }
        // ---- compute on stage c&1 ----
        const uint32_t ah_base = sb + (c & 1) * STAGE_BYTES;
        const uint32_t al_base = ah_base + OFF_ALO;
        const int kc = c * 64;
#pragma unroll
        for (int ks = 0; ks < 4; ks++) {
            uint32_t ah[2][4], al[2][4];
#pragma unroll
            for (int mt = 0; mt < 2; mt++) {
                uint32_t bo = SWZ128((uint32_t)(m0 + mt * 16 + r_lm) * 128 +
                                     ks * 32 + klane);
                ldsm_x4(ah[mt], ah_base + bo);
                ldsm_x4(al[mt], al_base + bo);
            }
            const int kof = kc + ks * 16 + bk;
#pragma unroll
            for (int nt = 0; nt < 4; nt++) {
                const int nrow = n0 + nt * 8 + bn;
                const __nv_bfloat16* ph = g_Whi + nrow * DIN + kof;
                const __nv_bfloat16* pl = g_Wlo + nrow * DIN + kof;
                uint32_t bh0 = *(const uint32_t*)(ph);
                uint32_t bh1 = *(const uint32_t*)(ph + 8);
                uint32_t bl0 = *(const uint32_t*)(pl);
                uint32_t bl1 = *(const uint32_t*)(pl + 8);
#pragma unroll
                for (int mt = 0; mt < 2; mt++) {
                    mma_bf16(acc[mt][nt], ah[mt], bh0, bh1);  // hi*Whi
                    mma_bf16(acc[mt][nt], ah[mt], bl0, bl1);  // hi*Wlo
                    mma_bf16(acc[mt][nt], al[mt], bh0, bh1);  // lo*Whi
                }
            }
        }
        __syncthreads();
        // ---- stage next chunk ----
        if (c < 3) {
            char* st = smem + ((c + 1) & 1) * STAGE_BYTES;
#pragma unroll
            for (int p = 0; p < 4; p++) {
                uint32_t rh[4], rl[4];
                float f[8] = {va[p][0].x, va[p][0].y, va[p][0].z, va[p][0].w,
                              va[p][1].x, va[p][1].y, va[p][1].z, va[p][1].w};
#pragma unroll
                for (int q = 0; q < 4; q++) {
                    uint32_t ha = hi_bits(f[2 * q]), hb = hi_bits(f[2 * q + 1]);
                    rh[q] = __byte_perm(ha, hb, 0x7632);
                    __nv_bfloat162 lo2 = __floats2bfloat162_rn(
                        f[2 * q] - __uint_as_float(ha), f[2 * q + 1] - __uint_as_float(hb));
                    rl[q] = *(uint32_t*)&lo2;
                }
                uint32_t bo = SWZ128((uint32_t)(srow + 32 * p) * 128 + g * 16);
                *(uint4*)(st + bo)           = make_uint4(rh[0], rh[1], rh[2], rh[3]);
                *(uint4*)(st + OFF_ALO + bo) = make_uint4(rl[0], rl[1], rl[2], rl[3]);
            }
            __syncthreads();
        }
    }

    // ---- epilogue: direct stores (quad-contiguous 32B per row) ----
#pragma unroll
    for (int mt = 0; mt < 2; mt++) {
        int r = row0 + m0 + mt * 16 + (lane >> 2);
#pragma unroll
        for (int nt = 0; nt < 4; nt++) {
            int col = n0 + nt * 8 + ((lane & 3) << 1);
            if (r < Ntot)
                *(float2*)(g_eprime + (size_t)r * DOUT + col) =
                    make_float2(acc[mt][nt][0], acc[mt][nt][1]);
            if (r + 8 < Ntot)
                *(float2*)(g_eprime + (size_t)(r + 8) * DOUT + col) =
                    make_float2(acc[mt][nt][2], acc[mt][nt][3]);
        }
    }
}

// ---------------- Phase 1b: s_src[n] = leaky_relu(e'[n] . a_src) -----------------
__global__ __launch_bounds__(256) void ssrc_kernel(const float* __restrict__ a_src,
                                                   int N) {
    int row  = blockIdx.x * 8 + (threadIdx.x >> 5);
    int lane = threadIdx.x & 31;
    if (row >= N) return;
    const float2* yr = (const float2*)(g_eprime + (size_t)row * DOUT);
    float2 v = yr[lane];
    float a0 = __ldg(&a_src[2 * lane]);
    float a1 = __ldg(&a_src[2 * lane + 1]);
    float p = v.x * a0 + v.y * a1;
#pragma unroll
    for (int o = 16; o; o >>= 1) p += __shfl_xor_sync(0xffffffffu, p, o);
    if (lane == 0) g_ssrc[row] = (p >= 0.f) ? p : 0.2f * p;
}

// ---------------- mask dtype probe: bool(1B) vs int32 ----------------------------
__global__ void detect_kernel(const unsigned char* __restrict__ m) {
    if (threadIdx.x == 0 && blockIdx.x == 0) {
        int f = 0;
        for (int i = 0; i < 256; i++)
            if ((i & 3) && m[i]) f = 1;
        g_mask_is_byte = f;
    }
}

// ---------------- Phase 2: masked softmax + weighted gather-sum ------------------
__global__ __launch_bounds__(256) void agg_kernel(const int* __restrict__ neighs,
                                                  const void* __restrict__ mask_raw,
                                                  float* __restrict__ out,
                                                  int B, int L) {
    __shared__ float sw[8][64];
    __shared__ int   sidx[8][64];

    const int w    = threadIdx.x >> 5;
    const int lane = threadIdx.x & 31;
    const int row  = blockIdx.x * 8 + w;
    if (row >= B) return;

    const bool maskb = (g_mask_is_byte != 0);
    const unsigned char* mk8  = (const unsigned char*)mask_raw + (size_t)row * L;
    const int*           mk32 = (const int*)mask_raw + (size_t)row * L;
    const int* nb = neighs + (size_t)row * L;

    int   i0 = 0, i1 = 0;
    float s0 = -3e38f, s1 = -3e38f;
    bool  v0 = false, v1 = false;
    if (lane < L) {
        v0 = maskb ? (mk8[lane] != 0) : (mk32[lane] != 0);
        if (v0) { i0 = nb[lane]; s0 = g_ssrc[i0]; }
    }
    int l1 = lane + 32;
    if (l1 < L) {
        v1 = maskb ? (mk8[l1] != 0) : (mk32[l1] != 0);
        if (v1) { i1 = nb[l1]; s1 = g_ssrc[i1]; }
    }

    float m = fmaxf(s0, s1);
#pragma unroll
    for (int o = 16; o; o >>= 1) m = fmaxf(m, __shfl_xor_sync(0xffffffffu, m, o));
    float e0 = v0 ? __expf(s0 - m) : 0.f;
    float e1 = v1 ? __expf(s1 - m) : 0.f;
    float ssum = e0 + e1;
#pragma unroll
    for (int o = 16; o; o >>= 1) ssum += __shfl_xor_sync(0xffffffffu, ssum, o);
    float inv = 1.0f / ssum;

    unsigned bal0 = __ballot_sync(0xffffffffu, v0);
    unsigned bal1 = __ballot_sync(0xffffffffu, v1);
    int c0  = __popc(bal0);
    int cnt = c0 + __popc(bal1);
    unsigned lt = (1u << lane) - 1u;
    if (v0) { int p = __popc(bal0 & lt);       sw[w][p] = e0 * inv; sidx[w][p] = i0; }
    if (v1) { int p = c0 + __popc(bal1 & lt);  sw[w][p] = e1 * inv; sidx[w][p] = i1; }
    __syncwarp();

    float acc0 = 0.f, acc1 = 0.f;
    for (int l = 0; l < cnt; l++) {
        float wgt = sw[w][l];
        const float2 v = *(const float2*)(g_eprime + (size_t)sidx[w][l] * DOUT + 2 * lane);
        acc0 = fmaf(wgt, v.x, acc0);
        acc1 = fmaf(wgt, v.y, acc1);
    }
    *(float2*)(&out[(size_t)row * DOUT + 2 * lane]) = make_float2(acc0, acc1);
}

// -----------------------------------------------------------------------------------
extern "C" void kernel_launch(void* const* d_in, const int* in_sizes, int n_in,
                              void* d_out, int out_size) {
    const int*   neighs = (const int*)d_in[0];
    const void*  mask   = d_in[1];
    const float* embed  = (const float*)d_in[3];
    const float* W      = (const float*)d_in[4];
    const float* a_src  = (const float*)d_in[5];

    const int B = in_sizes[2];
    const int L = in_sizes[0] / B;
    const int N = in_sizes[3] / DIN;

    cudaFuncSetAttribute(gemm_mma_kernel,
                         cudaFuncAttributeMaxDynamicSharedMemorySize, SMEM_TOTAL);

    wsplit_kernel<<<(DOUT * DIN + 255) / 256, 256>>>(W);
    gemm_mma_kernel<<<(N + 127) / 128, 256, SMEM_TOTAL>>>(embed, N);
    ssrc_kernel<<<(N + 7) / 8, 256>>>(a_src, N);
    detect_kernel<<<1, 32>>>((const unsigned char*)mask);
    agg_kernel<<<(B + 7) / 8, 256>>>(neighs, mask, (float*)d_out, B, L);
}

// round 4
// speedup vs baseline: 2.1940x; 1.8108x over previous
#include <cuda_runtime.h>
#include <cuda_bf16.h>
#include <cstdint>

#define DIN  256
#define DOUT 64
#define NMAX 200000

// ---------------- device scratch (no allocations allowed) ----------------------
__device__ float g_eprime[(size_t)NMAX * DOUT];
__device__ float g_ssrc[NMAX];
__device__ __nv_bfloat16 g_Whi[DOUT * DIN];
__device__ __nv_bfloat16 g_Wlo[DOUT * DIN];
__device__ int g_mask_is_byte;

// ---------------- helpers -------------------------------------------------------
__device__ __forceinline__ uint32_t smem_u32(const void* p) {
    uint32_t a;
    asm("{ .reg .u64 t; cvta.to.shared.u64 t, %1; cvt.u32.u64 %0, t; }" : "=r"(a) : "l"(p));
    return a;
}
#define SWZ128(bo) ((bo) ^ (((bo) >> 3) & 0x70))

__device__ __forceinline__ void ldsm_x4(uint32_t* r, uint32_t addr) {
    asm volatile("ldmatrix.sync.aligned.m8n8.x4.shared.b16 {%0,%1,%2,%3}, [%4];"
                 : "=r"(r[0]), "=r"(r[1]), "=r"(r[2]), "=r"(r[3]) : "r"(addr));
}
__device__ __forceinline__ void mma_bf16(float* c, const uint32_t* a,
                                         uint32_t b0, uint32_t b1) {
    asm volatile("mma.sync.aligned.m16n8k16.row.col.f32.bf16.bf16.f32 "
                 "{%0,%1,%2,%3}, {%4,%5,%6,%7}, {%8,%9}, {%0,%1,%2,%3};"
                 : "+f"(c[0]), "+f"(c[1]), "+f"(c[2]), "+f"(c[3])
                 : "r"(a[0]), "r"(a[1]), "r"(a[2]), "r"(a[3]), "r"(b0), "r"(b1));
}
// split a float into bf16 hi (round-half-up, 2 int ops) + fp32 residual
__device__ __forceinline__ uint32_t hi_bits(float x) {
    return (__float_as_uint(x) + 0x8000u) & 0xFFFF0000u;
}

// ---------------- smem layout (dynamic, 96 KB) ------------------------------------
// [0,32K): W hi  [32K,64K): W lo   (layout: [chunk c][64 n][128B k], SW128/blk)
// [64K,80K): A hi stage  [80K,96K): A lo stage  ([128 rows][128B], SW128)
#define OFF_WHI 0
#define OFF_WLO 32768
#define OFF_AHI 65536
#define OFF_ALO 81920
#define SMEM_TOTAL 98304

// ---------------- W split (once per launch) --------------------------------------
__global__ void wsplit_kernel(const float* __restrict__ W) {
    int i = blockIdx.x * 256 + threadIdx.x;
    if (i < DOUT * DIN) {
        float x  = W[i];
        float hf = __uint_as_float(hi_bits(x));
        g_Whi[i] = __float2bfloat16_rn(hf);
        g_Wlo[i] = __float2bfloat16_rn(x - hf);
    }
}

// ---------------- Phase 1: mma.sync bf16 3-pass GEMM + fused ssrc -----------------
__global__ __launch_bounds__(256, 2) void gemm_mma_kernel(const float* __restrict__ X,
                                                          const float* __restrict__ a_src,
                                                          int Ntot) {
    extern __shared__ char smem[];
    const uint32_t sb = smem_u32(smem);

    const int t    = threadIdx.x;
    const int lane = t & 31;
    const int wid  = t >> 5;
    const int row0 = blockIdx.x * 128;

    const int m0 = (wid & 3) * 32;   // warp m-offset
    const int n0 = (wid >> 2) * 32;  // warp n-offset

    // staging mapping
    const int srow = t >> 3, g = t & 7;
    // A ldmatrix lane geometry
    const int r_lm  = (lane & 7) | (((lane >> 3) & 1) << 3);
    const int klane = ((lane >> 4) & 1) * 16;
    // B ldmatrix lane geometry (non-trans on [n][k] rows)
    const int bn_lm = (lane & 7) + (((lane >> 4) & 1) << 3);
    const int bk_lm = ((lane >> 3) & 1) * 16;

    // a_src values for this lane's output columns
    float sa8[8];
#pragma unroll
    for (int nt = 0; nt < 4; nt++) {
        int col = n0 + nt * 8 + ((lane & 3) << 1);
        sa8[2 * nt]     = __ldg(&a_src[col]);
        sa8[2 * nt + 1] = __ldg(&a_src[col + 1]);
    }

    // ---- stage W (hi+lo, 64KB) into smem, swizzled per 128B row -------------------
#pragma unroll
    for (int i = 0; i < 8; i++) {
        int gidx = t + i * 256;                 // uint4 index into 32KB
        int n    = gidx >> 5;
        int rem  = (gidx & 31) * 16;            // byte offset in 512B global row
        int c    = rem >> 7;
        int kb   = rem & 127;
        uint32_t so = (uint32_t)c * 8192 + SWZ128((uint32_t)n * 128 + kb);
        *(uint4*)(smem + OFF_WHI + so) = *(const uint4*)((const char*)g_Whi + (size_t)gidx * 16);
        *(uint4*)(smem + OFF_WLO + so) = *(const uint4*)((const char*)g_Wlo + (size_t)gidx * 16);
    }

    float acc[2][4][4];
#pragma unroll
    for (int i = 0; i < 2; i++)
#pragma unroll
        for (int j = 0; j < 4; j++)
#pragma unroll
            for (int q = 0; q < 4; q++) acc[i][j][q] = 0.f;

    size_t grow[4];
#pragma unroll
    for (int p = 0; p < 4; p++) {
        int r = row0 + srow + 32 * p;
        grow[p] = (size_t)((r < Ntot) ? r : (Ntot - 1));
    }

    // ---- prologue: load + split + stage chunk 0 ----
    float4 va[4][2];
#pragma unroll
    for (int p = 0; p < 4; p++) {
        const float* src = X + grow[p] * DIN + g * 8;
        va[p][0] = *(const float4*)(src);
        va[p][1] = *(const float4*)(src + 4);
    }
#pragma unroll
    for (int p = 0; p < 4; p++) {
        uint32_t rh[4], rl[4];
        float f[8] = {va[p][0].x, va[p][0].y, va[p][0].z, va[p][0].w,
                      va[p][1].x, va[p][1].y, va[p][1].z, va[p][1].w};
#pragma unroll
        for (int q = 0; q < 4; q++) {
            uint32_t ha = hi_bits(f[2 * q]), hb = hi_bits(f[2 * q + 1]);
            rh[q] = __byte_perm(ha, hb, 0x7632);
            __nv_bfloat162 lo2 = __floats2bfloat162_rn(
                f[2 * q] - __uint_as_float(ha), f[2 * q + 1] - __uint_as_float(hb));
            rl[q] = *(uint32_t*)&lo2;
        }
        uint32_t bo = SWZ128((uint32_t)(srow + 32 * p) * 128 + g * 16);
        *(uint4*)(smem + OFF_AHI + bo) = make_uint4(rh[0], rh[1], rh[2], rh[3]);
        *(uint4*)(smem + OFF_ALO + bo) = make_uint4(rl[0], rl[1], rl[2], rl[3]);
    }
    __syncthreads();

    for (int c = 0; c < 4; c++) {
        // prefetch next chunk gmem (in flight during MMAs)
        if (c < 3) {
            const int kc = (c + 1) * 64;
#pragma unroll
            for (int p = 0; p < 4; p++) {
                const float* src = X + grow[p] * DIN + kc + g * 8;
                va[p][0] = *(const float4*)(src);
                va[p][1] = *(const float4*)(src + 4);
            }
        }
        const uint32_t ah_base = sb + OFF_AHI;
        const uint32_t al_base = sb + OFF_ALO;
        const uint32_t wh_base = sb + OFF_WHI + c * 8192;
        const uint32_t wl_base = sb + OFF_WLO + c * 8192;
#pragma unroll
        for (int ks = 0; ks < 4; ks++) {
            uint32_t ah[2][4], al[2][4], bh[8], bl[8];
#pragma unroll
            for (int mt = 0; mt < 2; mt++) {
                uint32_t bo = SWZ128((uint32_t)(m0 + mt * 16 + r_lm) * 128 +
                                     ks * 32 + klane);
                ldsm_x4(ah[mt], ah_base + bo);
                ldsm_x4(al[mt], al_base + bo);
            }
#pragma unroll
            for (int half = 0; half < 2; half++) {
                uint32_t bo = SWZ128((uint32_t)(n0 + half * 16 + bn_lm) * 128 +
                                     ks * 32 + bk_lm);
                ldsm_x4(bh + half * 4, wh_base + bo);
                ldsm_x4(bl + half * 4, wl_base + bo);
            }
#pragma unroll
            for (int nt = 0; nt < 4; nt++) {
                uint32_t bh0 = bh[2 * nt], bh1 = bh[2 * nt + 1];
                uint32_t bl0 = bl[2 * nt], bl1 = bl[2 * nt + 1];
#pragma unroll
                for (int mt = 0; mt < 2; mt++) {
                    mma_bf16(acc[mt][nt], ah[mt], bh0, bh1);
                    mma_bf16(acc[mt][nt], ah[mt], bl0, bl1);
                    mma_bf16(acc[mt][nt], al[mt], bh0, bh1);
                }
            }
        }
        if (c < 3) {
            __syncthreads();  // all warps done reading A stage
#pragma unroll
            for (int p = 0; p < 4; p++) {
                uint32_t rh[4], rl[4];
                float f[8] = {va[p][0].x, va[p][0].y, va[p][0].z, va[p][0].w,
                              va[p][1].x, va[p][1].y, va[p][1].z, va[p][1].w};
#pragma unroll
                for (int q = 0; q < 4; q++) {
                    uint32_t ha = hi_bits(f[2 * q]), hb = hi_bits(f[2 * q + 1]);
                    rh[q] = __byte_perm(ha, hb, 0x7632);
                    __nv_bfloat162 lo2 = __floats2bfloat162_rn(
                        f[2 * q] - __uint_as_float(ha), f[2 * q + 1] - __uint_as_float(hb));
                    rl[q] = *(uint32_t*)&lo2;
                }
                uint32_t bo = SWZ128((uint32_t)(srow + 32 * p) * 128 + g * 16);
                *(uint4*)(smem + OFF_AHI + bo) = make_uint4(rh[0], rh[1], rh[2], rh[3]);
                *(uint4*)(smem + OFF_ALO + bo) = make_uint4(rl[0], rl[1], rl[2], rl[3]);
            }
            __syncthreads();
        }
    }

    // ---- epilogue: stores + fused ssrc ------------------------------------------
#pragma unroll
    for (int mt = 0; mt < 2; mt++) {
        int r = row0 + m0 + mt * 16 + (lane >> 2);
#pragma unroll
        for (int nt = 0; nt < 4; nt++) {
            int col = n0 + nt * 8 + ((lane & 3) << 1);
            if (r < Ntot)
                *(float2*)(g_eprime + (size_t)r * DOUT + col) =
                    make_float2(acc[mt][nt][0], acc[mt][nt][1]);
            if (r + 8 < Ntot)
                *(float2*)(g_eprime + (size_t)(r + 8) * DOUT + col) =
                    make_float2(acc[mt][nt][2], acc[mt][nt][3]);
        }
    }
    // partial dot with a_src per row (32 cols per warp), quad-reduced
    __syncthreads();                 // A stage free -> reuse for partials
    float* part = (float*)(smem + OFF_AHI);   // [128][2]
#pragma unroll
    for (int mt = 0; mt < 2; mt++) {
        float p0 = 0.f, p1 = 0.f;
#pragma unroll
        for (int nt = 0; nt < 4; nt++) {
            p0 = fmaf(acc[mt][nt][0], sa8[2 * nt], p0);
            p0 = fmaf(acc[mt][nt][1], sa8[2 * nt + 1], p0);
            p1 = fmaf(acc[mt][nt][2], sa8[2 * nt], p1);
            p1 = fmaf(acc[mt][nt][3], sa8[2 * nt + 1], p1);
        }
        p0 += __shfl_xor_sync(0xffffffffu, p0, 1);
        p0 += __shfl_xor_sync(0xffffffffu, p0, 2);
        p1 += __shfl_xor_sync(0xffffffffu, p1, 1);
        p1 += __shfl_xor_sync(0xffffffffu, p1, 2);
        if ((lane & 3) == 0) {
            int rl0 = m0 + mt * 16 + (lane >> 2);
            part[rl0 * 2 + (n0 >> 5)]       = p0;
            part[(rl0 + 8) * 2 + (n0 >> 5)] = p1;
        }
    }
    __syncthreads();
    if (t < 128) {
        int gr = row0 + t;
        if (gr < Ntot) {
            float s = part[t * 2] + part[t * 2 + 1];
            g_ssrc[gr] = (s >= 0.f) ? s : 0.2f * s;
        }
    }
}

// ---------------- mask dtype probe: bool(1B) vs int32 ----------------------------
__global__ void detect_kernel(const unsigned char* __restrict__ m) {
    int t = threadIdx.x;
    int f = 0;
    for (int i = t; i < 256; i += 32)
        if ((i & 3) && m[i]) f = 1;
    unsigned b = __ballot_sync(0xffffffffu, f);
    if (t == 0) g_mask_is_byte = (b != 0);
}

// ---------------- Phase 2: masked softmax + weighted gather-sum ------------------
__global__ __launch_bounds__(256) void agg_kernel(const int* __restrict__ neighs,
                                                  const void* __restrict__ mask_raw,
                                                  float* __restrict__ out,
                                                  int B, int L) {
    __shared__ float sw[8][64];
    __shared__ int   sidx[8][64];

    const int w    = threadIdx.x >> 5;
    const int lane = threadIdx.x & 31;
    const int row  = blockIdx.x * 8 + w;
    if (row >= B) return;

    const bool maskb = (g_mask_is_byte != 0);
    const unsigned char* mk8  = (const unsigned char*)mask_raw + (size_t)row * L;
    const int*           mk32 = (const int*)mask_raw + (size_t)row * L;
    const int* nb = neighs + (size_t)row * L;

    int   i0 = 0, i1 = 0;
    float s0 = -3e38f, s1 = -3e38f;
    bool  v0 = false, v1 = false;
    if (lane < L) {
        v0 = maskb ? (mk8[lane] != 0) : (mk32[lane] != 0);
        if (v0) { i0 = nb[lane]; s0 = g_ssrc[i0]; }
    }
    int l1 = lane + 32;
    if (l1 < L) {
        v1 = maskb ? (mk8[l1] != 0) : (mk32[l1] != 0);
        if (v1) { i1 = nb[l1]; s1 = g_ssrc[i1]; }
    }

    float m = fmaxf(s0, s1);
#pragma unroll
    for (int o = 16; o; o >>= 1) m = fmaxf(m, __shfl_xor_sync(0xffffffffu, m, o));
    float e0 = v0 ? __expf(s0 - m) : 0.f;
    float e1 = v1 ? __expf(s1 - m) : 0.f;
    float ssum = e0 + e1;
#pragma unroll
    for (int o = 16; o; o >>= 1) ssum += __shfl_xor_sync(0xffffffffu, ssum, o);
    float inv = 1.0f / ssum;

    unsigned bal0 = __ballot_sync(0xffffffffu, v0);
    unsigned bal1 = __ballot_sync(0xffffffffu, v1);
    int c0  = __popc(bal0);
    int cnt = c0 + __popc(bal1);
    unsigned lt = (1u << lane) - 1u;
    if (v0) { int p = __popc(bal0 & lt);       sw[w][p] = e0 * inv; sidx[w][p] = i0; }
    if (v1) { int p = c0 + __popc(bal1 & lt);  sw[w][p] = e1 * inv; sidx[w][p] = i1; }
    __syncwarp();

    float acc0 = 0.f, acc1 = 0.f;
    for (int l = 0; l < cnt; l++) {
        float wgt = sw[w][l];
        const float2 v = *(const float2*)(g_eprime + (size_t)sidx[w][l] * DOUT + 2 * lane);
        acc0 = fmaf(wgt, v.x, acc0);
        acc1 = fmaf(wgt, v.y, acc1);
    }
    *(float2*)(&out[(size_t)row * DOUT + 2 * lane]) = make_float2(acc0, acc1);
}

// -----------------------------------------------------------------------------------
extern "C" void kernel_launch(void* const* d_in, const int* in_sizes, int n_in,
                              void* d_out, int out_size) {
    const int*   neighs = (const int*)d_in[0];
    const void*  mask   = d_in[1];
    const float* embed  = (const float*)d_in[3];
    const float* W      = (const float*)d_in[4];
    const float* a_src  = (const float*)d_in[5];

    const int B = in_sizes[2];
    const int L = in_sizes[0] / B;
    const int N = in_sizes[3] / DIN;

    cudaFuncSetAttribute(gemm_mma_kernel,
                         cudaFuncAttributeMaxDynamicSharedMemorySize, SMEM_TOTAL);

    wsplit_kernel<<<(DOUT * DIN + 255) / 256, 256>>>(W);
    gemm_mma_kernel<<<(N + 127) / 128, 256, SMEM_TOTAL>>>(embed, a_src, N);
    detect_kernel<<<1, 32>>>((const unsigned char*)mask);
    agg_kernel<<<(B + 7) / 8, 256>>>(neighs, mask, (float*)d_out, B, L);
}